// round 8
// baseline (speedup 1.0000x reference)
#include <cuda_runtime.h>
#include <math_constants.h>

// Fixed shapes
#define B     32
#define H     8192
#define HO    4096
#define W4    64          // 256 floats / 4
#define ROWS  16          // output rows per tile (per batch) per block
#define RPT   4           // output rows per thread per tile (ROWS / 4 subs)
#define GPB   256         // blocks per batch (HO / ROWS)
#define NPAIR (B / 2)     // 16 batch pairs
#define NBLK  (NPAIR * GPB)   // 4096 blocks

// Per-batch state; static-initialized, self-reset by last normalizer per batch.
__device__ unsigned g_min[B] = {
    0xFFFFFFFFu,0xFFFFFFFFu,0xFFFFFFFFu,0xFFFFFFFFu,0xFFFFFFFFu,0xFFFFFFFFu,0xFFFFFFFFu,0xFFFFFFFFu,
    0xFFFFFFFFu,0xFFFFFFFFu,0xFFFFFFFFu,0xFFFFFFFFu,0xFFFFFFFFu,0xFFFFFFFFu,0xFFFFFFFFu,0xFFFFFFFFu,
    0xFFFFFFFFu,0xFFFFFFFFu,0xFFFFFFFFu,0xFFFFFFFFu,0xFFFFFFFFu,0xFFFFFFFFu,0xFFFFFFFFu,0xFFFFFFFFu,
    0xFFFFFFFFu,0xFFFFFFFFu,0xFFFFFFFFu,0xFFFFFFFFu,0xFFFFFFFFu,0xFFFFFFFFu,0xFFFFFFFFu,0xFFFFFFFFu};
__device__ unsigned g_max[B];    // zero-init == encoded -inf
__device__ int g_pool_cnt[B];    // zero-init
__device__ int g_done_cnt[B];    // zero-init

__device__ __forceinline__ unsigned enc_f(float f) {
    unsigned u = __float_as_uint(f);
    return (u & 0x80000000u) ? ~u : (u | 0x80000000u);
}
__device__ __forceinline__ float dec_f(unsigned e) {
    unsigned u = (e & 0x80000000u) ? (e ^ 0x80000000u) : ~e;
    return __uint_as_float(u);
}

__global__ __launch_bounds__(256, 6)
void fused_kernel(const float4* __restrict__ x, float4* __restrict__ out) {
    __shared__ float4 tileA[ROWS * W4];    // 16 KiB (batch b0)
    __shared__ float4 tileB[ROWS * W4];    // 16 KiB (batch b1)
    __shared__ float  s_mn[8], s_mx[8];

    const int tid  = threadIdx.x;
    const int w4   = tid & 63;
    const int sub  = tid >> 6;            // 0..3
    const int lane = tid & 31;
    const int wid  = tid >> 5;

    const int pair = blockIdx.x >> 8;     // 0..15
    const int grp  = blockIdx.x & (GPB - 1);
    const int b0   = 2 * pair;
    const int b1   = 2 * pair + 1;
    const int r0   = grp * ROWS + sub * RPT;   // first output row for this thread
    const int lr0  = sub * RPT;                // local row in tile

    // ================= pool one batch's tile + publish ====================
    #define POOL_TILE(bb, TILE)                                              \
    {                                                                        \
        const float4* __restrict__ xb = x + (size_t)(bb) * H * W4;           \
        float4 prev;                                                         \
        if (r0 == 0) {                                                       \
            prev = make_float4(-CUDART_INF_F, -CUDART_INF_F,                 \
                               -CUDART_INF_F, -CUDART_INF_F);                \
        } else {                                                             \
            prev = __ldcs(&xb[(size_t)(2 * r0 - 1) * W4 + w4]);              \
        }                                                                    \
        float mn =  CUDART_INF_F;                                            \
        float mx = -CUDART_INF_F;                                            \
        _Pragma("unroll")                                                    \
        for (int i = 0; i < RPT; i++) {                                      \
            const int r = r0 + i;                                            \
            float4 a = __ldcs(&xb[(size_t)(2 * r)     * W4 + w4]);           \
            float4 c = __ldcs(&xb[(size_t)(2 * r + 1) * W4 + w4]);           \
            float4 p;                                                        \
            p.x = fmaxf(fmaxf(a.x, c.x), prev.x);                            \
            p.y = fmaxf(fmaxf(a.y, c.y), prev.y);                            \
            p.z = fmaxf(fmaxf(a.z, c.z), prev.z);                            \
            p.w = fmaxf(fmaxf(a.w, c.w), prev.w);                            \
            TILE[(lr0 + i) * W4 + w4] = p;                                   \
            mn = fminf(mn, fminf(fminf(p.x, p.y), fminf(p.z, p.w)));         \
            mx = fmaxf(mx, fmaxf(fmaxf(p.x, p.y), fmaxf(p.z, p.w)));        \
            prev = c;                                                        \
        }                                                                    \
        _Pragma("unroll")                                                    \
        for (int off = 16; off > 0; off >>= 1) {                             \
            mn = fminf(mn, __shfl_xor_sync(0xFFFFFFFFu, mn, off));           \
            mx = fmaxf(mx, __shfl_xor_sync(0xFFFFFFFFu, mx, off));           \
        }                                                                    \
        if (lane == 0) { s_mn[wid] = mn; s_mx[wid] = mx; }                   \
        __syncthreads();                                                     \
        if (wid == 0) {                                                      \
            mn = (lane < 8) ? s_mn[lane] :  CUDART_INF_F;                    \
            mx = (lane < 8) ? s_mx[lane] : -CUDART_INF_F;                    \
            _Pragma("unroll")                                                \
            for (int off = 4; off > 0; off >>= 1) {                          \
                mn = fminf(mn, __shfl_xor_sync(0xFFFFFFFFu, mn, off));       \
                mx = fmaxf(mx, __shfl_xor_sync(0xFFFFFFFFu, mx, off));       \
            }                                                                \
            if (lane == 0) {                                                 \
                atomicMin(&g_min[bb], enc_f(mn));                            \
                atomicMax(&g_max[bb], enc_f(mx));                            \
                __threadfence();   /* single-thread: order the 2 atomics */  \
                atomicAdd(&g_pool_cnt[bb], 1);                               \
            }                                                                \
        }                                                                    \
        __syncthreads();   /* s_mn/s_mx reuse safety */                      \
    }

    // ============ wait + normalize one batch's tile + self-reset ==========
    #define NORM_TILE(bb, TILE)                                              \
    {                                                                        \
        if (tid == 0) {                                                      \
            while (*(volatile int*)&g_pool_cnt[bb] < GPB) __nanosleep(64);   \
        }                                                                    \
        __syncthreads();                                                     \
        const float mnv = dec_f(*(volatile unsigned*)&g_min[bb]);            \
        const float mxv = dec_f(*(volatile unsigned*)&g_max[bb]);            \
        const float inv = 1.0f / (mxv - mnv);                                \
        float4* __restrict__ ob = out + (size_t)(bb) * HO * W4;              \
        _Pragma("unroll")                                                    \
        for (int i = 0; i < RPT; i++) {                                      \
            float4 p = TILE[(lr0 + i) * W4 + w4];  /* own writes */          \
            p.x = (p.x - mnv) * inv;                                         \
            p.y = (p.y - mnv) * inv;                                         \
            p.z = (p.z - mnv) * inv;                                         \
            p.w = (p.w - mnv) * inv;                                         \
            __stcs(&ob[(size_t)(r0 + i) * W4 + w4], p);                      \
        }                                                                    \
        __syncthreads();                                                     \
        if (tid == 0) {                                                      \
            int d = atomicAdd(&g_done_cnt[bb], 1);                           \
            if (d == GPB - 1) {    /* last normalizer: reset for replay */   \
                *(volatile unsigned*)&g_min[bb] = 0xFFFFFFFFu;               \
                *(volatile unsigned*)&g_max[bb] = 0x00000000u;               \
                *(volatile int*)&g_pool_cnt[bb] = 0;                         \
                *(volatile int*)&g_done_cnt[bb] = 0;                         \
                __threadfence();                                             \
            }                                                                \
        }                                                                    \
    }

    // Pipeline: pool b0, pool b1 (hides b0's skew), then norm b0, norm b1.
    POOL_TILE(b0, tileA)
    POOL_TILE(b1, tileB)
    NORM_TILE(b0, tileA)
    NORM_TILE(b1, tileB)

    #undef POOL_TILE
    #undef NORM_TILE
}

extern "C" void kernel_launch(void* const* d_in, const int* in_sizes, int n_in,
                              void* d_out, int out_size) {
    (void)in_sizes; (void)n_in; (void)out_size;
    const float4* x = (const float4*)d_in[0];
    float4* out = (float4*)d_out;
    fused_kernel<<<NBLK, 256>>>(x, out);
}